// round 9
// baseline (speedup 1.0000x reference)
#include <cuda_runtime.h>
#include <cuda_bf16.h>
#include <math.h>
#include <stdint.h>

#define BSZ   4
#define LSEQ  2048
#define DH    1024
#define MROWS (BSZ * LSEQ)   // 8192

// ---------------------------------------------------------------------------
// bf16 hi/lo scratch (static device arrays: no runtime allocs)
// ---------------------------------------------------------------------------
__device__ __nv_bfloat16 g_xh[(size_t)MROWS * DH],  g_xl[(size_t)MROWS * DH];
__device__ __nv_bfloat16 g_Wqh[(size_t)DH * DH],    g_Wql[(size_t)DH * DH];
__device__ __nv_bfloat16 g_Wkh[(size_t)DH * DH],    g_Wkl[(size_t)DH * DH];
__device__ __nv_bfloat16 g_Wvh[(size_t)DH * DH],    g_Wvl[(size_t)DH * DH];
__device__ __nv_bfloat16 g_Qh[(size_t)MROWS * DH],  g_Ql[(size_t)MROWS * DH];
__device__ __nv_bfloat16 g_Kh[(size_t)MROWS * DH],  g_Kl[(size_t)MROWS * DH];
__device__ __nv_bfloat16 g_Vth[(size_t)MROWS * DH], g_Vtl[(size_t)MROWS * DH]; // [b][d][l]
__device__ __nv_bfloat16 g_Sh[(size_t)MROWS * LSEQ], g_Sl[(size_t)MROWS * LSEQ];

// ---------------------------------------------------------------------------
// PTX helpers — ONLY arch-neutral instructions (sm_80+ baseline ISA).
// ---------------------------------------------------------------------------
__device__ __forceinline__ uint32_t smem_to_u32(const void* p) {
    uint32_t a;
    asm("{ .reg .u64 t; cvta.to.shared.u64 t, %1; cvt.u32.u64 %0, t; }"
        : "=r"(a) : "l"(p));
    return a;
}
#define CP_ASYNC16(smem, gptr) \
    asm volatile("cp.async.ca.shared.global [%0], [%1], 16;" \
                 :: "r"(smem), "l"(gptr))
#define CP_COMMIT() asm volatile("cp.async.commit_group;")
#define CP_WAIT(n)  asm volatile("cp.async.wait_group %0;" :: "n"(n))

#define LDMATRIX_X4(r, addr) \
    asm volatile("ldmatrix.sync.aligned.m8n8.x4.shared.b16 {%0,%1,%2,%3}, [%4];" \
                 : "=r"((r)[0]), "=r"((r)[1]), "=r"((r)[2]), "=r"((r)[3]) \
                 : "r"(addr))

#define MMA_BF16(c, a, b0v, b1v) \
    asm volatile("mma.sync.aligned.m16n8k16.row.col.f32.bf16.bf16.f32 " \
                 "{%0,%1,%2,%3}, {%4,%5,%6,%7}, {%8,%9}, {%0,%1,%2,%3};" \
                 : "+f"((c)[0]), "+f"((c)[1]), "+f"((c)[2]), "+f"((c)[3]) \
                 : "r"((a)[0]), "r"((a)[1]), "r"((a)[2]), "r"((a)[3]), \
                   "r"(b0v), "r"(b1v))

// ---------------------------------------------------------------------------
// Split-bf16 tensor-core GEMM (NT): C = scale*(A·B^T) + bias + causal
// CTA tile 128x128, BK=32, 8 warps (2x4), warp tile 64x32, cp.async 2-stage.
// causal: skip fully-masked tiles (n0 >= m0+128) entirely.
// trik:   restrict K to m0+128 (A columns beyond are exactly zero).
// mode 0: Cf fp32; mode 1: split bf16 hi/lo; mode 2: split transposed-batched.
// ---------------------------------------------------------------------------
#define ROWB      80
#define MAT_BYTES 10240
#define STG_BYTES (4 * MAT_BYTES)
#define SMEM_BYTES (2 * STG_BYTES)

__global__ __launch_bounds__(256) void gemm_mma(
    const __nv_bfloat16* __restrict__ Ah, const __nv_bfloat16* __restrict__ Al,
    const __nv_bfloat16* __restrict__ Bh, const __nv_bfloat16* __restrict__ Bl,
    const float* __restrict__ bias,
    float* __restrict__ Cf, __nv_bfloat16* __restrict__ Ch, __nv_bfloat16* __restrict__ Cl,
    int K, int ldc,
    long long sA, long long sB, long long sC,
    float scale, int causal, int trik, int mode)
{
    extern __shared__ char smem[];
    const uint32_t sbase = smem_to_u32(smem);
    const int tid  = threadIdx.x;
    const int wid  = tid >> 5;
    const int lane = tid & 31;
    const int wm   = wid >> 2;       // 0..1 -> m offset wm*64
    const int wn   = wid & 3;        // 0..3 -> n offset wn*32
    const int m0   = blockIdx.y * 128;
    const int n0   = blockIdx.x * 128;
    const int z    = blockIdx.z;

    // Fully-masked score tile: softmax will write exact zeros; skip everything.
    if (causal && n0 >= m0 + 128) return;

    const __nv_bfloat16* pAh = Ah + z * sA + (size_t)m0 * K;
    const __nv_bfloat16* pAl = Al + z * sA + (size_t)m0 * K;
    const __nv_bfloat16* pBh = Bh + z * sB + (size_t)n0 * K;
    const __nv_bfloat16* pBl = Bl + z * sB + (size_t)n0 * K;

    // wts columns beyond row index are exactly zero -> truncate K.
    const int Ke = trik ? ((m0 + 128 < K) ? m0 + 128 : K) : K;

    auto issue = [&](int i) {
        const int k0 = i << 5;
        const uint32_t st = sbase + (i & 1) * STG_BYTES;
#pragma unroll
        for (int half = 0; half < 2; half++) {
            int e = tid + half * 256;
            int r = e >> 2, c = e & 3;
            uint32_t so = st + (uint32_t)(r * ROWB + c * 16);
            size_t go = (size_t)r * K + k0 + c * 8;
            CP_ASYNC16(so,                 pAh + go);
            CP_ASYNC16(so + 1 * MAT_BYTES, pAl + go);
            CP_ASYNC16(so + 2 * MAT_BYTES, pBh + go);
            CP_ASYNC16(so + 3 * MAT_BYTES, pBl + go);
        }
        CP_COMMIT();
    };

    float acc[4][4][4];
#pragma unroll
    for (int mi = 0; mi < 4; mi++)
#pragma unroll
        for (int ni = 0; ni < 4; ni++)
#pragma unroll
            for (int q = 0; q < 4; q++) acc[mi][ni][q] = 0.0f;

    const int niters = Ke >> 5;
    issue(0);

    for (int i = 0; i < niters; i++) {
        if (i + 1 < niters) { issue(i + 1); CP_WAIT(1); }
        else                { CP_WAIT(0); }
        __syncthreads();

        const uint32_t st = sbase + (i & 1) * STG_BYTES;
#pragma unroll
        for (int ks = 0; ks < 2; ks++) {
            uint32_t ah[4][4], al[4][4], bh[4][2], bl[4][2];
            const uint32_t kcol = (uint32_t)((ks * 2 + (lane >> 4)) * 16);
#pragma unroll
            for (int mi = 0; mi < 4; mi++) {
                uint32_t addr = st + (uint32_t)((wm * 64 + mi * 16 + (lane & 15)) * ROWB) + kcol;
                LDMATRIX_X4(ah[mi], addr);
                LDMATRIX_X4(al[mi], addr + MAT_BYTES);
            }
#pragma unroll
            for (int p = 0; p < 2; p++) {
                uint32_t addr = st + 2 * MAT_BYTES +
                    (uint32_t)((wn * 32 + p * 16 + (lane & 15)) * ROWB) + kcol;
                uint32_t t[4];
                LDMATRIX_X4(t, addr);
                bh[p * 2 + 0][0] = t[0]; bh[p * 2 + 0][1] = t[2];
                bh[p * 2 + 1][0] = t[1]; bh[p * 2 + 1][1] = t[3];
                LDMATRIX_X4(t, addr + MAT_BYTES);
                bl[p * 2 + 0][0] = t[0]; bl[p * 2 + 0][1] = t[2];
                bl[p * 2 + 1][0] = t[1]; bl[p * 2 + 1][1] = t[3];
            }
#pragma unroll
            for (int mi = 0; mi < 4; mi++)
#pragma unroll
                for (int ni = 0; ni < 4; ni++) {
                    MMA_BF16(acc[mi][ni], ah[mi], bh[ni][0], bh[ni][1]);
                    MMA_BF16(acc[mi][ni], ah[mi], bl[ni][0], bl[ni][1]);
                    MMA_BF16(acc[mi][ni], al[mi], bh[ni][0], bh[ni][1]);
                }
        }
        __syncthreads();
    }

    // ---- Epilogue ----
#pragma unroll
    for (int mi = 0; mi < 4; mi++) {
#pragma unroll
        for (int ni = 0; ni < 4; ni++) {
            const int row0 = m0 + wm * 64 + mi * 16 + (lane >> 2);
            const int col0 = n0 + wn * 32 + ni * 8 + 2 * (lane & 3);
            float bsum0 = bias ? bias[col0]     : 0.0f;
            float bsum1 = bias ? bias[col0 + 1] : 0.0f;
#pragma unroll
            for (int h = 0; h < 2; h++) {
                const int row = row0 + h * 8;
                float v0 = acc[mi][ni][h * 2 + 0] * scale + bsum0;
                float v1 = acc[mi][ni][h * 2 + 1] * scale + bsum1;
                if (causal) {
                    v0 += (col0     > row) ? -999.0f : 0.0f;
                    v1 += (col0 + 1 > row) ? -999.0f : 0.0f;
                }
                if (mode == 0) {
                    float2 o = {v0, v1};
                    *(float2*)(Cf + z * sC + (size_t)row * ldc + col0) = o;
                } else if (mode == 1) {
                    __nv_bfloat16 h0 = __float2bfloat16(v0);
                    __nv_bfloat16 h1 = __float2bfloat16(v1);
                    __nv_bfloat16 l0 = __float2bfloat16(v0 - __bfloat162float(h0));
                    __nv_bfloat16 l1 = __float2bfloat16(v1 - __bfloat162float(h1));
                    __nv_bfloat162 ph2; ph2.x = h0; ph2.y = h1;
                    __nv_bfloat162 pl2; pl2.x = l0; pl2.y = l1;
                    *(__nv_bfloat162*)(Ch + (size_t)row * ldc + col0) = ph2;
                    *(__nv_bfloat162*)(Cl + (size_t)row * ldc + col0) = pl2;
                } else {
                    const int b = row >> 11, l = row & 2047;
                    __nv_bfloat16 h0 = __float2bfloat16(v0);
                    __nv_bfloat16 h1 = __float2bfloat16(v1);
                    __nv_bfloat16 l0 = __float2bfloat16(v0 - __bfloat162float(h0));
                    __nv_bfloat16 l1 = __float2bfloat16(v1 - __bfloat162float(h1));
                    size_t i0 = ((size_t)b * DH + col0) * LSEQ + l;
                    Ch[i0] = h0; Cl[i0] = l0;
                    Ch[i0 + LSEQ] = h1; Cl[i0 + LSEQ] = l1;
                }
            }
        }
    }
}

// ---------------------------------------------------------------------------
// fp32 -> bf16 hi/lo split (elementwise, vectorized)
// ---------------------------------------------------------------------------
__global__ __launch_bounds__(256) void split_f32(
    const float4* __restrict__ src, __nv_bfloat162* __restrict__ hi,
    __nv_bfloat162* __restrict__ lo, int n4)
{
    int i = blockIdx.x * 256 + threadIdx.x;
    if (i >= n4) return;
    float4 v = src[i];
    __nv_bfloat16 h0 = __float2bfloat16(v.x), h1 = __float2bfloat16(v.y);
    __nv_bfloat16 h2 = __float2bfloat16(v.z), h3 = __float2bfloat16(v.w);
    __nv_bfloat16 l0 = __float2bfloat16(v.x - __bfloat162float(h0));
    __nv_bfloat16 l1 = __float2bfloat16(v.y - __bfloat162float(h1));
    __nv_bfloat16 l2 = __float2bfloat16(v.z - __bfloat162float(h2));
    __nv_bfloat16 l3 = __float2bfloat16(v.w - __bfloat162float(h3));
    __nv_bfloat162 a; a.x = h0; a.y = h1;
    __nv_bfloat162 b; b.x = h2; b.y = h3;
    __nv_bfloat162 c; c.x = l0; c.y = l1;
    __nv_bfloat162 d; d.x = l2; d.y = l3;
    hi[i * 2] = a; hi[i * 2 + 1] = b;
    lo[i * 2] = c; lo[i * 2 + 1] = d;
}

// ---------------------------------------------------------------------------
// Fused causal softmax + bf16 hi/lo split. One block per row (8192 rows).
// Reads ONLY cols 0..r (upper triangle of scores was never computed);
// writes softmax to wts (exact zeros for cols > r) and split bf16 to Sh/Sl.
// ---------------------------------------------------------------------------
__global__ __launch_bounds__(256) void softmax_split_rows(
    float* __restrict__ w, __nv_bfloat16* __restrict__ Sh, __nv_bfloat16* __restrict__ Sl)
{
    const int rowg = blockIdx.x;            // 0..MROWS-1
    const int r    = rowg & (LSEQ - 1);     // row within batch = causal bound
    float* p = w + (size_t)rowg * LSEQ;
    __nv_bfloat16* sh = Sh + (size_t)rowg * LSEQ;
    __nv_bfloat16* sl = Sl + (size_t)rowg * LSEQ;

    const int t = threadIdx.x, lane = t & 31, wrp = t >> 5;
    __shared__ float red[8];

    float v[8];
    float mx = -INFINITY;
#pragma unroll
    for (int i = 0; i < 8; i++) {
        int col = t + 256 * i;
        v[i] = (col <= r) ? p[col] : -INFINITY;
        mx = fmaxf(mx, v[i]);
    }
#pragma unroll
    for (int s = 16; s > 0; s >>= 1) mx = fmaxf(mx, __shfl_xor_sync(0xffffffffu, mx, s));
    if (lane == 0) red[wrp] = mx;
    __syncthreads();
    mx = red[0];
#pragma unroll
    for (int i = 1; i < 8; i++) mx = fmaxf(mx, red[i]);

    float sum = 0.0f;
#pragma unroll
    for (int i = 0; i < 8; i++) {
        int col = t + 256 * i;
        v[i] = (col <= r) ? __expf(v[i] - mx) : 0.0f;
        sum += v[i];
    }
#pragma unroll
    for (int s = 16; s > 0; s >>= 1) sum += __shfl_xor_sync(0xffffffffu, sum, s);
    __syncthreads();
    if (lane == 0) red[wrp] = sum;
    __syncthreads();
    sum = 0.0f;
#pragma unroll
    for (int i = 0; i < 8; i++) sum += red[i];

    float inv = 1.0f / sum;
#pragma unroll
    for (int i = 0; i < 8; i++) {
        int col = t + 256 * i;
        float o = v[i] * inv;
        p[col] = o;
        __nv_bfloat16 h = __float2bfloat16(o);
        sh[col] = h;
        sl[col] = __float2bfloat16(o - __bfloat162float(h));
    }
}

// ---------------------------------------------------------------------------
// Launch
// ---------------------------------------------------------------------------
extern "C" void kernel_launch(void* const* d_in, const int* in_sizes, int n_in,
                              void* d_out, int out_size)
{
    (void)in_sizes; (void)n_in; (void)out_size;
    const float* x  = (const float*)d_in[0];
    const float* Wq = (const float*)d_in[1];
    const float* bq = (const float*)d_in[2];
    const float* Wk = (const float*)d_in[3];
    const float* bk = (const float*)d_in[4];
    const float* Wv = (const float*)d_in[5];
    const float* bv = (const float*)d_in[6];

    float* out = (float*)d_out;
    float* wts = out + (size_t)MROWS * DH;

    cudaFuncSetAttribute(gemm_mma, cudaFuncAttributeMaxDynamicSharedMemorySize, SMEM_BYTES);

    __nv_bfloat16 *xh, *xl, *Wqh, *Wql, *Wkh, *Wkl, *Wvh, *Wvl;
    __nv_bfloat16 *Qh, *Ql, *Kh, *Kl, *Vth, *Vtl, *Sh, *Sl;
    cudaGetSymbolAddress((void**)&xh,  g_xh);  cudaGetSymbolAddress((void**)&xl,  g_xl);
    cudaGetSymbolAddress((void**)&Wqh, g_Wqh); cudaGetSymbolAddress((void**)&Wql, g_Wql);
    cudaGetSymbolAddress((void**)&Wkh, g_Wkh); cudaGetSymbolAddress((void**)&Wkl, g_Wkl);
    cudaGetSymbolAddress((void**)&Wvh, g_Wvh); cudaGetSymbolAddress((void**)&Wvl, g_Wvl);
    cudaGetSymbolAddress((void**)&Qh,  g_Qh);  cudaGetSymbolAddress((void**)&Ql,  g_Ql);
    cudaGetSymbolAddress((void**)&Kh,  g_Kh);  cudaGetSymbolAddress((void**)&Kl,  g_Kl);
    cudaGetSymbolAddress((void**)&Vth, g_Vth); cudaGetSymbolAddress((void**)&Vtl, g_Vtl);
    cudaGetSymbolAddress((void**)&Sh,  g_Sh);  cudaGetSymbolAddress((void**)&Sl,  g_Sl);

    // 1) splits of x and weights
    {
        int n4 = MROWS * DH / 4;
        split_f32<<<(n4 + 255) / 256, 256>>>((const float4*)x,
            (__nv_bfloat162*)xh, (__nv_bfloat162*)xl, n4);
        int w4 = DH * DH / 4;
        split_f32<<<(w4 + 255) / 256, 256>>>((const float4*)Wq,
            (__nv_bfloat162*)Wqh, (__nv_bfloat162*)Wql, w4);
        split_f32<<<(w4 + 255) / 256, 256>>>((const float4*)Wk,
            (__nv_bfloat162*)Wkh, (__nv_bfloat162*)Wkl, w4);
        split_f32<<<(w4 + 255) / 256, 256>>>((const float4*)Wv,
            (__nv_bfloat162*)Wvh, (__nv_bfloat162*)Wvl, w4);
    }

    dim3 blk(256);

    // 2) QKV projections (M=8192, N=1024, K=1024)
    dim3 gq(DH / 128, MROWS / 128, 1);
    gemm_mma<<<gq, blk, SMEM_BYTES>>>(xh, xl, Wqh, Wql, bq,
        nullptr, Qh, Ql, DH, DH, 0, 0, 0, 1.0f, 0, 0, 1);
    gemm_mma<<<gq, blk, SMEM_BYTES>>>(xh, xl, Wkh, Wkl, bk,
        nullptr, Kh, Kl, DH, DH, 0, 0, 0, 1.0f, 0, 0, 1);
    gemm_mma<<<gq, blk, SMEM_BYTES>>>(xh, xl, Wvh, Wvl, bv,
        nullptr, Vth, Vtl, DH, DH, 0, 0, 0, 1.0f, 0, 0, 2);  // V stored transposed

    // 3) scores = Q K^T / 32 + causal(-999); fully-masked tiles skipped
    dim3 gs(LSEQ / 128, LSEQ / 128, BSZ);
    gemm_mma<<<gs, blk, SMEM_BYTES>>>(Qh, Ql, Kh, Kl, nullptr,
        wts, nullptr, nullptr, DH, LSEQ,
        (long long)LSEQ * DH, (long long)LSEQ * DH, (long long)LSEQ * LSEQ,
        1.0f / 32.0f, 1, 0, 0);

    // 4) fused causal softmax + split (reads lower triangle only; zeros the rest)
    softmax_split_rows<<<MROWS, 256>>>(wts, Sh, Sl);

    // 5) out = wts @ V -> NT with Vt; K truncated to causal bound per row tile
    dim3 go(DH / 128, LSEQ / 128, BSZ);
    gemm_mma<<<go, blk, SMEM_BYTES>>>(Sh, Sl, Vth, Vtl, nullptr,
        out, nullptr, nullptr, LSEQ, DH,
        (long long)LSEQ * LSEQ, (long long)DH * LSEQ, (long long)LSEQ * DH,
        1.0f, 0, 1, 0);
}

// round 13
// speedup vs baseline: 1.5898x; 1.5898x over previous
#include <cuda_runtime.h>
#include <cuda_bf16.h>
#include <math.h>
#include <stdint.h>

#define BSZ   4
#define LSEQ  2048
#define DH    1024
#define MROWS (BSZ * LSEQ)   // 8192

// ---------------------------------------------------------------------------
// bf16 hi/lo scratch (static device arrays: no runtime allocs)
// ---------------------------------------------------------------------------
__device__ __nv_bfloat16 g_xh[(size_t)MROWS * DH],  g_xl[(size_t)MROWS * DH];
__device__ __nv_bfloat16 g_Wqh[(size_t)DH * DH],    g_Wql[(size_t)DH * DH];
__device__ __nv_bfloat16 g_Wkh[(size_t)DH * DH],    g_Wkl[(size_t)DH * DH];
__device__ __nv_bfloat16 g_Wvh[(size_t)DH * DH],    g_Wvl[(size_t)DH * DH];
__device__ __nv_bfloat16 g_Qh[(size_t)MROWS * DH],  g_Ql[(size_t)MROWS * DH];
__device__ __nv_bfloat16 g_Kh[(size_t)MROWS * DH],  g_Kl[(size_t)MROWS * DH];
__device__ __nv_bfloat16 g_Vth[(size_t)MROWS * DH], g_Vtl[(size_t)MROWS * DH]; // [b][d][l]
__device__ __nv_bfloat16 g_Sh[(size_t)MROWS * LSEQ], g_Sl[(size_t)MROWS * LSEQ];

// ---------------------------------------------------------------------------
// PTX helpers — ONLY arch-neutral instructions (sm_80+ baseline ISA).
// ---------------------------------------------------------------------------
__device__ __forceinline__ uint32_t smem_to_u32(const void* p) {
    uint32_t a;
    asm("{ .reg .u64 t; cvta.to.shared.u64 t, %1; cvt.u32.u64 %0, t; }"
        : "=r"(a) : "l"(p));
    return a;
}
#define CP_ASYNC16(smem, gptr) \
    asm volatile("cp.async.ca.shared.global [%0], [%1], 16;" \
                 :: "r"(smem), "l"(gptr))
#define CP_COMMIT() asm volatile("cp.async.commit_group;")
#define CP_WAIT(n)  asm volatile("cp.async.wait_group %0;" :: "n"(n))

#define LDMATRIX_X4(r, addr) \
    asm volatile("ldmatrix.sync.aligned.m8n8.x4.shared.b16 {%0,%1,%2,%3}, [%4];" \
                 : "=r"((r)[0]), "=r"((r)[1]), "=r"((r)[2]), "=r"((r)[3]) \
                 : "r"(addr))

#define MMA_BF16(c, a, b0v, b1v) \
    asm volatile("mma.sync.aligned.m16n8k16.row.col.f32.bf16.bf16.f32 " \
                 "{%0,%1,%2,%3}, {%4,%5,%6,%7}, {%8,%9}, {%0,%1,%2,%3};" \
                 : "+f"((c)[0]), "+f"((c)[1]), "+f"((c)[2]), "+f"((c)[3]) \
                 : "r"((a)[0]), "r"((a)[1]), "r"((a)[2]), "r"((a)[3]), \
                   "r"(b0v), "r"(b1v))

// ---------------------------------------------------------------------------
// Split-bf16 tensor-core GEMM (NT): C = scale*(A·B^T) + bias + causal
// CTA tile 128x128, BK=32, 8 warps (2x4), warp tile 64x32, cp.async 2-stage.
// causal: skip fully-masked tiles (n0 >= m0+128) entirely.
// trik:   restrict K to m0+128 (A cols beyond are exactly zero); y-order is
//         REVERSED so heavy (large-K) tiles launch in wave 1.
// mode 0: Cf fp32; mode 1: split bf16 hi/lo; mode 2: split transposed-batched
//         (staged through smem for coalesced stores along l).
// ---------------------------------------------------------------------------
#define ROWB      80
#define MAT_BYTES 10240
#define STG_BYTES (4 * MAT_BYTES)
#define SMEM_BYTES (2 * STG_BYTES)

__global__ __launch_bounds__(256) void gemm_mma(
    const __nv_bfloat16* __restrict__ Ah, const __nv_bfloat16* __restrict__ Al,
    const __nv_bfloat16* __restrict__ Bh, const __nv_bfloat16* __restrict__ Bl,
    const float* __restrict__ bias,
    float* __restrict__ Cf, __nv_bfloat16* __restrict__ Ch, __nv_bfloat16* __restrict__ Cl,
    int K, int ldc,
    long long sA, long long sB, long long sC,
    float scale, int causal, int trik, int mode)
{
    extern __shared__ char smem[];
    const uint32_t sbase = smem_to_u32(smem);
    const int tid  = threadIdx.x;
    const int wid  = tid >> 5;
    const int lane = tid & 31;
    const int wm   = wid >> 2;       // 0..1 -> m offset wm*64
    const int wn   = wid & 3;        // 0..3 -> n offset wn*32
    // trik: reversed y order so large-K tiles go first (wave balance).
    const int m0   = (trik ? (gridDim.y - 1 - blockIdx.y) : blockIdx.y) * 128;
    const int n0   = blockIdx.x * 128;
    const int z    = blockIdx.z;

    // Fully-masked score tile: softmax writes exact zeros there; skip.
    if (causal && n0 >= m0 + 128) return;

    const __nv_bfloat16* pAh = Ah + z * sA + (size_t)m0 * K;
    const __nv_bfloat16* pAl = Al + z * sA + (size_t)m0 * K;
    const __nv_bfloat16* pBh = Bh + z * sB + (size_t)n0 * K;
    const __nv_bfloat16* pBl = Bl + z * sB + (size_t)n0 * K;

    // wts columns beyond row index are exactly zero -> truncate K.
    const int Ke = trik ? ((m0 + 128 < K) ? m0 + 128 : K) : K;

    auto issue = [&](int i) {
        const int k0 = i << 5;
        const uint32_t st = sbase + (i & 1) * STG_BYTES;
#pragma unroll
        for (int half = 0; half < 2; half++) {
            int e = tid + half * 256;
            int r = e >> 2, c = e & 3;
            uint32_t so = st + (uint32_t)(r * ROWB + c * 16);
            size_t go = (size_t)r * K + k0 + c * 8;
            CP_ASYNC16(so,                 pAh + go);
            CP_ASYNC16(so + 1 * MAT_BYTES, pAl + go);
            CP_ASYNC16(so + 2 * MAT_BYTES, pBh + go);
            CP_ASYNC16(so + 3 * MAT_BYTES, pBl + go);
        }
        CP_COMMIT();
    };

    float acc[4][4][4];
#pragma unroll
    for (int mi = 0; mi < 4; mi++)
#pragma unroll
        for (int ni = 0; ni < 4; ni++)
#pragma unroll
            for (int q = 0; q < 4; q++) acc[mi][ni][q] = 0.0f;

    const int niters = Ke >> 5;
    issue(0);

    for (int i = 0; i < niters; i++) {
        if (i + 1 < niters) { issue(i + 1); CP_WAIT(1); }
        else                { CP_WAIT(0); }
        __syncthreads();

        const uint32_t st = sbase + (i & 1) * STG_BYTES;
#pragma unroll
        for (int ks = 0; ks < 2; ks++) {
            uint32_t ah[4][4], al[4][4], bh[4][2], bl[4][2];
            const uint32_t kcol = (uint32_t)((ks * 2 + (lane >> 4)) * 16);
#pragma unroll
            for (int mi = 0; mi < 4; mi++) {
                uint32_t addr = st + (uint32_t)((wm * 64 + mi * 16 + (lane & 15)) * ROWB) + kcol;
                LDMATRIX_X4(ah[mi], addr);
                LDMATRIX_X4(al[mi], addr + MAT_BYTES);
            }
#pragma unroll
            for (int p = 0; p < 2; p++) {
                uint32_t addr = st + 2 * MAT_BYTES +
                    (uint32_t)((wn * 32 + p * 16 + (lane & 15)) * ROWB) + kcol;
                uint32_t t[4];
                LDMATRIX_X4(t, addr);
                bh[p * 2 + 0][0] = t[0]; bh[p * 2 + 0][1] = t[2];
                bh[p * 2 + 1][0] = t[1]; bh[p * 2 + 1][1] = t[3];
                LDMATRIX_X4(t, addr + MAT_BYTES);
                bl[p * 2 + 0][0] = t[0]; bl[p * 2 + 0][1] = t[2];
                bl[p * 2 + 1][0] = t[1]; bl[p * 2 + 1][1] = t[3];
            }
#pragma unroll
            for (int mi = 0; mi < 4; mi++)
#pragma unroll
                for (int ni = 0; ni < 4; ni++) {
                    MMA_BF16(acc[mi][ni], ah[mi], bh[ni][0], bh[ni][1]);
                    MMA_BF16(acc[mi][ni], ah[mi], bl[ni][0], bl[ni][1]);
                    MMA_BF16(acc[mi][ni], al[mi], bh[ni][0], bh[ni][1]);
                }
        }
        __syncthreads();
    }

    // ---- Epilogue ----
    if (mode == 2) {
        // Stage fp32 tile in smem [col][row] (pad 132), then store coalesced
        // along l. Tile rows never cross a batch boundary (128 | 2048).
        float* fsm = (float*)smem;
#pragma unroll
        for (int mi = 0; mi < 4; mi++)
#pragma unroll
            for (int ni = 0; ni < 4; ni++) {
                const int rowl = wm * 64 + mi * 16 + (lane >> 2);
                const int coll = wn * 32 + ni * 8 + 2 * (lane & 3);
                float b0 = bias ? bias[n0 + coll]     : 0.0f;
                float b1 = bias ? bias[n0 + coll + 1] : 0.0f;
#pragma unroll
                for (int h = 0; h < 2; h++) {
                    fsm[(coll + 0) * 132 + rowl + h * 8] = acc[mi][ni][h * 2 + 0] * scale + b0;
                    fsm[(coll + 1) * 132 + rowl + h * 8] = acc[mi][ni][h * 2 + 1] * scale + b1;
                }
            }
        __syncthreads();
        const int b  = m0 >> 11;
        const int l0 = m0 & (LSEQ - 1);
#pragma unroll
        for (int c = 0; c < 16; c++) {
            const int coll = wid + c * 8;
            const size_t obase = ((size_t)b * DH + n0 + coll) * LSEQ + l0;
#pragma unroll
            for (int rr = 0; rr < 4; rr++) {
                const int rowl = lane + rr * 32;
                float v = fsm[coll * 132 + rowl];
                __nv_bfloat16 hh = __float2bfloat16(v);
                Ch[obase + rowl] = hh;
                Cl[obase + rowl] = __float2bfloat16(v - __bfloat162float(hh));
            }
        }
        return;
    }

#pragma unroll
    for (int mi = 0; mi < 4; mi++) {
#pragma unroll
        for (int ni = 0; ni < 4; ni++) {
            const int row0 = m0 + wm * 64 + mi * 16 + (lane >> 2);
            const int col0 = n0 + wn * 32 + ni * 8 + 2 * (lane & 3);
            float bsum0 = bias ? bias[col0]     : 0.0f;
            float bsum1 = bias ? bias[col0 + 1] : 0.0f;
#pragma unroll
            for (int h = 0; h < 2; h++) {
                const int row = row0 + h * 8;
                float v0 = acc[mi][ni][h * 2 + 0] * scale + bsum0;
                float v1 = acc[mi][ni][h * 2 + 1] * scale + bsum1;
                if (causal) {
                    v0 += (col0     > row) ? -999.0f : 0.0f;
                    v1 += (col0 + 1 > row) ? -999.0f : 0.0f;
                }
                if (mode == 0) {
                    float2 o = {v0, v1};
                    *(float2*)(Cf + z * sC + (size_t)row * ldc + col0) = o;
                } else {
                    __nv_bfloat16 h0 = __float2bfloat16(v0);
                    __nv_bfloat16 h1 = __float2bfloat16(v1);
                    __nv_bfloat16 l0 = __float2bfloat16(v0 - __bfloat162float(h0));
                    __nv_bfloat16 l1 = __float2bfloat16(v1 - __bfloat162float(h1));
                    __nv_bfloat162 ph2; ph2.x = h0; ph2.y = h1;
                    __nv_bfloat162 pl2; pl2.x = l0; pl2.y = l1;
                    *(__nv_bfloat162*)(Ch + (size_t)row * ldc + col0) = ph2;
                    *(__nv_bfloat162*)(Cl + (size_t)row * ldc + col0) = pl2;
                }
            }
        }
    }
}

// ---------------------------------------------------------------------------
// fp32 -> bf16 hi/lo split (elementwise, vectorized)
// ---------------------------------------------------------------------------
__global__ __launch_bounds__(256) void split_f32(
    const float4* __restrict__ src, __nv_bfloat162* __restrict__ hi,
    __nv_bfloat162* __restrict__ lo, int n4)
{
    int i = blockIdx.x * 256 + threadIdx.x;
    if (i >= n4) return;
    float4 v = src[i];
    __nv_bfloat16 h0 = __float2bfloat16(v.x), h1 = __float2bfloat16(v.y);
    __nv_bfloat16 h2 = __float2bfloat16(v.z), h3 = __float2bfloat16(v.w);
    __nv_bfloat16 l0 = __float2bfloat16(v.x - __bfloat162float(h0));
    __nv_bfloat16 l1 = __float2bfloat16(v.y - __bfloat162float(h1));
    __nv_bfloat16 l2 = __float2bfloat16(v.z - __bfloat162float(h2));
    __nv_bfloat16 l3 = __float2bfloat16(v.w - __bfloat162float(h3));
    __nv_bfloat162 a; a.x = h0; a.y = h1;
    __nv_bfloat162 b; b.x = h2; b.y = h3;
    __nv_bfloat162 c; c.x = l0; c.y = l1;
    __nv_bfloat162 d; d.x = l2; d.y = l3;
    hi[i * 2] = a; hi[i * 2 + 1] = b;
    lo[i * 2] = c; lo[i * 2 + 1] = d;
}

// ---------------------------------------------------------------------------
// Fused causal softmax + bf16 hi/lo split. One block per row (8192 rows).
// Reads ONLY cols 0..r; writes softmax to wts (exact zeros beyond) + Sh/Sl.
// ---------------------------------------------------------------------------
__global__ __launch_bounds__(256) void softmax_split_rows(
    float* __restrict__ w, __nv_bfloat16* __restrict__ Sh, __nv_bfloat16* __restrict__ Sl)
{
    const int rowg = blockIdx.x;
    const int r    = rowg & (LSEQ - 1);
    float* p = w + (size_t)rowg * LSEQ;
    __nv_bfloat16* sh = Sh + (size_t)rowg * LSEQ;
    __nv_bfloat16* sl = Sl + (size_t)rowg * LSEQ;

    const int t = threadIdx.x, lane = t & 31, wrp = t >> 5;
    __shared__ float red[8];

    float v[8];
    float mx = -INFINITY;
#pragma unroll
    for (int i = 0; i < 8; i++) {
        int col = t + 256 * i;
        v[i] = (col <= r) ? p[col] : -INFINITY;
        mx = fmaxf(mx, v[i]);
    }
#pragma unroll
    for (int s = 16; s > 0; s >>= 1) mx = fmaxf(mx, __shfl_xor_sync(0xffffffffu, mx, s));
    if (lane == 0) red[wrp] = mx;
    __syncthreads();
    mx = red[0];
#pragma unroll
    for (int i = 1; i < 8; i++) mx = fmaxf(mx, red[i]);

    float sum = 0.0f;
#pragma unroll
    for (int i = 0; i < 8; i++) {
        int col = t + 256 * i;
        v[i] = (col <= r) ? __expf(v[i] - mx) : 0.0f;
        sum += v[i];
    }
#pragma unroll
    for (int s = 16; s > 0; s >>= 1) sum += __shfl_xor_sync(0xffffffffu, sum, s);
    __syncthreads();
    if (lane == 0) red[wrp] = sum;
    __syncthreads();
    sum = 0.0f;
#pragma unroll
    for (int i = 0; i < 8; i++) sum += red[i];

    float inv = 1.0f / sum;
#pragma unroll
    for (int i = 0; i < 8; i++) {
        int col = t + 256 * i;
        float o = v[i] * inv;
        p[col] = o;
        __nv_bfloat16 h = __float2bfloat16(o);
        sh[col] = h;
        sl[col] = __float2bfloat16(o - __bfloat162float(h));
    }
}

// ---------------------------------------------------------------------------
// Launch
// ---------------------------------------------------------------------------
extern "C" void kernel_launch(void* const* d_in, const int* in_sizes, int n_in,
                              void* d_out, int out_size)
{
    (void)in_sizes; (void)n_in; (void)out_size;
    const float* x  = (const float*)d_in[0];
    const float* Wq = (const float*)d_in[1];
    const float* bq = (const float*)d_in[2];
    const float* Wk = (const float*)d_in[3];
    const float* bk = (const float*)d_in[4];
    const float* Wv = (const float*)d_in[5];
    const float* bv = (const float*)d_in[6];

    float* out = (float*)d_out;
    float* wts = out + (size_t)MROWS * DH;

    cudaFuncSetAttribute(gemm_mma, cudaFuncAttributeMaxDynamicSharedMemorySize, SMEM_BYTES);

    __nv_bfloat16 *xh, *xl, *Wqh, *Wql, *Wkh, *Wkl, *Wvh, *Wvl;
    __nv_bfloat16 *Qh, *Ql, *Kh, *Kl, *Vth, *Vtl, *Sh, *Sl;
    cudaGetSymbolAddress((void**)&xh,  g_xh);  cudaGetSymbolAddress((void**)&xl,  g_xl);
    cudaGetSymbolAddress((void**)&Wqh, g_Wqh); cudaGetSymbolAddress((void**)&Wql, g_Wql);
    cudaGetSymbolAddress((void**)&Wkh, g_Wkh); cudaGetSymbolAddress((void**)&Wkl, g_Wkl);
    cudaGetSymbolAddress((void**)&Wvh, g_Wvh); cudaGetSymbolAddress((void**)&Wvl, g_Wvl);
    cudaGetSymbolAddress((void**)&Qh,  g_Qh);  cudaGetSymbolAddress((void**)&Ql,  g_Ql);
    cudaGetSymbolAddress((void**)&Kh,  g_Kh);  cudaGetSymbolAddress((void**)&Kl,  g_Kl);
    cudaGetSymbolAddress((void**)&Vth, g_Vth); cudaGetSymbolAddress((void**)&Vtl, g_Vtl);
    cudaGetSymbolAddress((void**)&Sh,  g_Sh);  cudaGetSymbolAddress((void**)&Sl,  g_Sl);

    // 1) splits of x and weights
    {
        int n4 = MROWS * DH / 4;
        split_f32<<<(n4 + 255) / 256, 256>>>((const float4*)x,
            (__nv_bfloat162*)xh, (__nv_bfloat162*)xl, n4);
        int w4 = DH * DH / 4;
        split_f32<<<(w4 + 255) / 256, 256>>>((const float4*)Wq,
            (__nv_bfloat162*)Wqh, (__nv_bfloat162*)Wql, w4);
        split_f32<<<(w4 + 255) / 256, 256>>>((const float4*)Wk,
            (__nv_bfloat162*)Wkh, (__nv_bfloat162*)Wkl, w4);
        split_f32<<<(w4 + 255) / 256, 256>>>((const float4*)Wv,
            (__nv_bfloat162*)Wvh, (__nv_bfloat162*)Wvl, w4);
    }

    dim3 blk(256);

    // 2) QKV projections (M=8192, N=1024, K=1024)
    dim3 gq(DH / 128, MROWS / 128, 1);
    gemm_mma<<<gq, blk, SMEM_BYTES>>>(xh, xl, Wqh, Wql, bq,
        nullptr, Qh, Ql, DH, DH, 0, 0, 0, 1.0f, 0, 0, 1);
    gemm_mma<<<gq, blk, SMEM_BYTES>>>(xh, xl, Wkh, Wkl, bk,
        nullptr, Kh, Kl, DH, DH, 0, 0, 0, 1.0f, 0, 0, 1);
    gemm_mma<<<gq, blk, SMEM_BYTES>>>(xh, xl, Wvh, Wvl, bv,
        nullptr, Vth, Vtl, DH, DH, 0, 0, 0, 1.0f, 0, 0, 2);  // V stored transposed

    // 3) scores = Q K^T / 32 + causal(-999); fully-masked tiles skipped
    dim3 gs(LSEQ / 128, LSEQ / 128, BSZ);
    gemm_mma<<<gs, blk, SMEM_BYTES>>>(Qh, Ql, Kh, Kl, nullptr,
        wts, nullptr, nullptr, DH, LSEQ,
        (long long)LSEQ * DH, (long long)LSEQ * DH, (long long)LSEQ * LSEQ,
        1.0f / 32.0f, 1, 0, 0);

    // 4) fused causal softmax + split
    softmax_split_rows<<<MROWS, 256>>>(wts, Sh, Sl);

    // 5) out = wts @ V -> NT with Vt; K truncated per row tile, big tiles first
    dim3 go(DH / 128, LSEQ / 128, BSZ);
    gemm_mma<<<go, blk, SMEM_BYTES>>>(Sh, Sl, Vth, Vtl, nullptr,
        out, nullptr, nullptr, LSEQ, DH,
        (long long)LSEQ * LSEQ, (long long)DH * LSEQ, (long long)LSEQ * DH,
        1.0f, 0, 1, 0);
}